// round 1
// baseline (speedup 1.0000x reference)
#include <cuda_runtime.h>

typedef unsigned long long u64;

#define D_MODEL 1024
#define S_LEN   2048
#define NBATCH  4
#define NH      16
#define DKH     64
#define M_TOT   (NBATCH * S_LEN)   /* 8192 */

// Scratch for projected Q, K, V (B,S,D) fp32 — static device arrays (no allocs).
__device__ float g_Q[(size_t)M_TOT * D_MODEL];
__device__ float g_K[(size_t)M_TOT * D_MODEL];
__device__ float g_V[(size_t)M_TOT * D_MODEL];

// ---------------- packed f32x2 helpers (Blackwell sm_103a) ----------------
__device__ __forceinline__ u64 pk2(float lo, float hi) {
    u64 r; asm("mov.b64 %0,{%1,%2};" : "=l"(r) : "f"(lo), "f"(hi)); return r;
}
__device__ __forceinline__ u64 fma2(u64 a, u64 b, u64 c) {
    u64 d; asm("fma.rn.f32x2 %0,%1,%2,%3;" : "=l"(d) : "l"(a), "l"(b), "l"(c)); return d;
}
__device__ __forceinline__ u64 mul2(u64 a, u64 b) {
    u64 d; asm("mul.rn.f32x2 %0,%1,%2;" : "=l"(d) : "l"(a), "l"(b)); return d;
}
__device__ __forceinline__ void unpk(u64 a, float& x, float& y) {
    asm("mov.b64 {%0,%1},%2;" : "=f"(x), "=f"(y) : "l"(a));
}

// =========================================================================
// Projection GEMM:  out[m,n] = sum_d Xa[m,d]*Wa[n,d] + Xb[m,d]*Wb[n,d]
//                            + ba[n] + bb[n]
// 128x128 CTA tile, K-chunk 16, 256 threads, 8x8 per thread via f32x2.
// =========================================================================
__global__ __launch_bounds__(256) void proj_kernel(
    const float* __restrict__ Xa, const float* __restrict__ Xb,
    const float* __restrict__ Wa, const float* __restrict__ Wb,
    const float* __restrict__ ba, const float* __restrict__ bb,
    float* __restrict__ outp)
{
    __shared__ float As[16][132];   // As[k][m] (transposed), pad 4 floats
    __shared__ float Bs[16][132];   // Bs[k][n]

    const int t  = threadIdx.x;
    const int tx = t & 15, ty = t >> 4;
    const int m0 = blockIdx.x * 128;
    const int n0 = blockIdx.y * 128;

    const int lrow0 = t >> 2;   // 0..63
    const int lseg  = t & 3;    // 0..3 (16-byte segment within 16-float k-chunk)

    u64 acc[8][4];
    #pragma unroll
    for (int i = 0; i < 8; ++i)
        #pragma unroll
        for (int j = 0; j < 4; ++j) acc[i][j] = 0ull;

    #pragma unroll 1
    for (int pass = 0; pass < 2; ++pass) {
        const float* X = pass ? Xb : Xa;
        const float* W = pass ? Wb : Wa;
        #pragma unroll 1
        for (int k0 = 0; k0 < D_MODEL; k0 += 16) {
            __syncthreads();
            #pragma unroll
            for (int l = 0; l < 2; ++l) {
                int row = lrow0 + l * 64;
                float4 av = *(const float4*)&X[(size_t)(m0 + row) * D_MODEL + k0 + lseg * 4];
                As[lseg*4+0][row] = av.x; As[lseg*4+1][row] = av.y;
                As[lseg*4+2][row] = av.z; As[lseg*4+3][row] = av.w;
                float4 bv = *(const float4*)&W[(size_t)(n0 + row) * D_MODEL + k0 + lseg * 4];
                Bs[lseg*4+0][row] = bv.x; Bs[lseg*4+1][row] = bv.y;
                Bs[lseg*4+2][row] = bv.z; Bs[lseg*4+3][row] = bv.w;
            }
            __syncthreads();
            #pragma unroll
            for (int kk = 0; kk < 16; ++kk) {
                float4 a0 = *(const float4*)&As[kk][ty * 4];
                float4 a1 = *(const float4*)&As[kk][64 + ty * 4];
                u64 b0 = *(const u64*)&Bs[kk][tx * 4];
                u64 b1 = *(const u64*)&Bs[kk][tx * 4 + 2];
                u64 b2 = *(const u64*)&Bs[kk][64 + tx * 4];
                u64 b3 = *(const u64*)&Bs[kk][64 + tx * 4 + 2];
                float am[8] = {a0.x, a0.y, a0.z, a0.w, a1.x, a1.y, a1.z, a1.w};
                #pragma unroll
                for (int i = 0; i < 8; ++i) {
                    u64 ad = pk2(am[i], am[i]);
                    acc[i][0] = fma2(ad, b0, acc[i][0]);
                    acc[i][1] = fma2(ad, b1, acc[i][1]);
                    acc[i][2] = fma2(ad, b2, acc[i][2]);
                    acc[i][3] = fma2(ad, b3, acc[i][3]);
                }
            }
        }
    }

    #pragma unroll
    for (int i = 0; i < 8; ++i) {
        int m = m0 + ((i < 4) ? (ty * 4 + i) : (64 + ty * 4 + (i - 4)));
        #pragma unroll
        for (int nh = 0; nh < 2; ++nh) {
            int cb = n0 + nh * 64 + tx * 4;
            float x0, x1, x2, x3;
            unpk(acc[i][nh * 2 + 0], x0, x1);
            unpk(acc[i][nh * 2 + 1], x2, x3);
            float4 st;
            st.x = x0 + ba[cb + 0] + bb[cb + 0];
            st.y = x1 + ba[cb + 1] + bb[cb + 1];
            st.z = x2 + ba[cb + 2] + bb[cb + 2];
            st.w = x3 + ba[cb + 3] + bb[cb + 3];
            *(float4*)&outp[(size_t)m * D_MODEL + cb] = st;
        }
    }
}

// =========================================================================
// Flash attention, fp32, f32x2 inner products.
// Grid: (S/64 q-tiles, B*H).  256 threads; thread (tx,ty) owns
// 4 query rows (ty*4..) x 4 key cols / 4 dk cols (tx*4..).
// Smem: Qs[d][r], Ks[d][c], Ps[c][r], Vs[c][d] each 64x68 fp32.
// =========================================================================
#define AT_PAD 68
#define ATTN_SMEM (4 * 64 * AT_PAD * 4)   /* 69632 B */

__global__ __launch_bounds__(256) void attn_kernel(
    const float* __restrict__ Q, const float* __restrict__ K,
    const float* __restrict__ V, float* __restrict__ out,
    const float* __restrict__ biasp)
{
    extern __shared__ float sm[];
    float (*Qs)[AT_PAD] = (float(*)[AT_PAD])(sm);
    float (*Ks)[AT_PAD] = (float(*)[AT_PAD])(sm + 64 * AT_PAD);
    float (*Ps)[AT_PAD] = (float(*)[AT_PAD])(sm + 2 * 64 * AT_PAD);
    float (*Vs)[AT_PAD] = (float(*)[AT_PAD])(sm + 3 * 64 * AT_PAD);

    const int t  = threadIdx.x;
    const int tx = t & 15, ty = t >> 4;
    const int q0 = blockIdx.x * 64;
    const int bh = blockIdx.y;
    const int b  = bh >> 4, h = bh & 15;
    const size_t base = (size_t)b * S_LEN * D_MODEL + (size_t)h * DKH;
    const float bias  = biasp[0];
    const float NEGINF = __int_as_float(0xff800000);

    // Load Q tile (64 rows x 64 dk) transposed into Qs[d][r].
    #pragma unroll
    for (int l = 0; l < 4; ++l) {
        int f = t + l * 256;
        int r = f >> 4, seg = f & 15;
        float4 v = *(const float4*)&Q[base + (size_t)(q0 + r) * D_MODEL + seg * 4];
        Qs[seg*4+0][r] = v.x; Qs[seg*4+1][r] = v.y;
        Qs[seg*4+2][r] = v.z; Qs[seg*4+3][r] = v.w;
    }

    float mrow[4], lrow[4];
    u64 oacc[4][2];
    #pragma unroll
    for (int r = 0; r < 4; ++r) {
        mrow[r] = NEGINF; lrow[r] = 0.f;
        oacc[r][0] = 0ull; oacc[r][1] = 0ull;
    }

    #pragma unroll 1
    for (int kb = 0; kb < S_LEN / 64; ++kb) {
        const int c0 = kb * 64;
        __syncthreads();   // prior PV reads of Ks/Vs/Ps complete
        #pragma unroll
        for (int l = 0; l < 4; ++l) {
            int f = t + l * 256;
            int r = f >> 4, seg = f & 15;
            float4 kv = *(const float4*)&K[base + (size_t)(c0 + r) * D_MODEL + seg * 4];
            Ks[seg*4+0][r] = kv.x; Ks[seg*4+1][r] = kv.y;
            Ks[seg*4+2][r] = kv.z; Ks[seg*4+3][r] = kv.w;
            float4 vv = *(const float4*)&V[base + (size_t)(c0 + r) * D_MODEL + seg * 4];
            *(float4*)&Vs[r][seg * 4] = vv;
        }
        __syncthreads();   // also covers initial Qs stores on kb==0

        // ---- S = Q K^T (4x4 per thread) ----
        u64 sacc[4][2];
        #pragma unroll
        for (int r = 0; r < 4; ++r) { sacc[r][0] = 0ull; sacc[r][1] = 0ull; }
        #pragma unroll 8
        for (int d = 0; d < 64; ++d) {
            float4 q = *(const float4*)&Qs[d][ty * 4];
            u64 k0 = *(const u64*)&Ks[d][tx * 4];
            u64 k1 = *(const u64*)&Ks[d][tx * 4 + 2];
            float qa[4] = {q.x, q.y, q.z, q.w};
            #pragma unroll
            for (int r = 0; r < 4; ++r) {
                u64 qd = pk2(qa[r], qa[r]);
                sacc[r][0] = fma2(qd, k0, sacc[r][0]);
                sacc[r][1] = fma2(qd, k1, sacc[r][1]);
            }
        }

        // ---- online softmax (rows reduced across the 16 tx lanes) ----
        #pragma unroll
        for (int r = 0; r < 4; ++r) {
            float s0, s1, s2, s3;
            unpk(sacc[r][0], s0, s1);
            unpk(sacc[r][1], s2, s3);
            s0 = s0 * 0.125f + bias; s1 = s1 * 0.125f + bias;
            s2 = s2 * 0.125f + bias; s3 = s3 * 0.125f + bias;
            float mx = fmaxf(fmaxf(s0, s1), fmaxf(s2, s3));
            #pragma unroll
            for (int o = 1; o < 16; o <<= 1)
                mx = fmaxf(mx, __shfl_xor_sync(0xffffffffu, mx, o));
            float mnew = fmaxf(mrow[r], mx);
            float p0 = __expf(s0 - mnew), p1 = __expf(s1 - mnew);
            float p2 = __expf(s2 - mnew), p3 = __expf(s3 - mnew);
            float ls = (p0 + p1) + (p2 + p3);
            #pragma unroll
            for (int o = 1; o < 16; o <<= 1)
                ls += __shfl_xor_sync(0xffffffffu, ls, o);
            float fac = __expf(mrow[r] - mnew);
            lrow[r] = lrow[r] * fac + ls;
            mrow[r] = mnew;
            u64 fd = pk2(fac, fac);
            oacc[r][0] = mul2(oacc[r][0], fd);
            oacc[r][1] = mul2(oacc[r][1], fd);
            Ps[tx*4+0][ty*4+r] = p0;
            Ps[tx*4+1][ty*4+r] = p1;
            Ps[tx*4+2][ty*4+r] = p2;
            Ps[tx*4+3][ty*4+r] = p3;
        }
        __syncthreads();

        // ---- O += P V ----
        #pragma unroll 8
        for (int c = 0; c < 64; ++c) {
            float4 p = *(const float4*)&Ps[c][ty * 4];
            u64 v0 = *(const u64*)&Vs[c][tx * 4];
            u64 v1 = *(const u64*)&Vs[c][tx * 4 + 2];
            float pa[4] = {p.x, p.y, p.z, p.w};
            #pragma unroll
            for (int r = 0; r < 4; ++r) {
                u64 pd = pk2(pa[r], pa[r]);
                oacc[r][0] = fma2(pd, v0, oacc[r][0]);
                oacc[r][1] = fma2(pd, v1, oacc[r][1]);
            }
        }
    }

    #pragma unroll
    for (int r = 0; r < 4; ++r) {
        float inv = 1.0f / lrow[r];
        float o0, o1, o2, o3;
        unpk(oacc[r][0], o0, o1);
        unpk(oacc[r][1], o2, o3);
        float4 st = {o0 * inv, o1 * inv, o2 * inv, o3 * inv};
        *(float4*)&out[base + (size_t)(q0 + ty * 4 + r) * D_MODEL + tx * 4] = st;
    }
}

// =========================================================================
extern "C" void kernel_launch(void* const* d_in, const int* in_sizes, int n_in,
                              void* d_out, int out_size)
{
    (void)in_sizes; (void)n_in; (void)out_size;
    const float* Xs   = (const float*)d_in[0];
    const float* Xt   = (const float*)d_in[1];
    const float* W_qs = (const float*)d_in[2];
    const float* b_qs = (const float*)d_in[3];
    const float* W_qt = (const float*)d_in[4];
    const float* b_qt = (const float*)d_in[5];
    const float* W_ks = (const float*)d_in[6];
    const float* b_ks = (const float*)d_in[7];
    const float* W_kt = (const float*)d_in[8];
    const float* b_kt = (const float*)d_in[9];
    const float* W_vs = (const float*)d_in[10];
    const float* b_vs = (const float*)d_in[11];
    const float* W_vt = (const float*)d_in[12];
    const float* b_vt = (const float*)d_in[13];
    const float* abias = (const float*)d_in[14];
    float* out = (float*)d_out;

    float *Qp, *Kp, *Vp;
    cudaGetSymbolAddress((void**)&Qp, g_Q);
    cudaGetSymbolAddress((void**)&Kp, g_K);
    cudaGetSymbolAddress((void**)&Vp, g_V);

    dim3 pg(M_TOT / 128, D_MODEL / 128);   // (64, 8)
    proj_kernel<<<pg, 256>>>(Xs, Xt, W_qs, W_qt, b_qs, b_qt, Qp);
    proj_kernel<<<pg, 256>>>(Xs, Xt, W_ks, W_kt, b_ks, b_kt, Kp);
    proj_kernel<<<pg, 256>>>(Xs, Xt, W_vs, W_vt, b_vs, b_vt, Vp);

    cudaFuncSetAttribute(attn_kernel,
                         cudaFuncAttributeMaxDynamicSharedMemorySize, ATTN_SMEM);
    attn_kernel<<<dim3(S_LEN / 64, NBATCH * NH), 256, ATTN_SMEM>>>(
        Qp, Kp, Vp, out, abias);
}

// round 8
// speedup vs baseline: 1.5337x; 1.5337x over previous
#include <cuda_runtime.h>
#include <cstdint>

typedef unsigned long long u64;
typedef unsigned int u32;

#define D_MODEL 1024
#define S_LEN   2048
#define NBATCH  4
#define NH      16
#define DKH     64
#define M_TOT   (NBATCH * S_LEN)   /* 8192 */
#define K_TOT   2048               /* concat of Xs|Xt feature dims */

// Scratch (no allocs): tf32-rounded operands + projected Q/K/V.
__device__ float g_A[(size_t)M_TOT * K_TOT];            // [Xs|Xt], rna-tf32
__device__ float g_W[3][(size_t)D_MODEL * K_TOT];       // [W_zs|W_zt], rna-tf32
__device__ float g_Q[(size_t)M_TOT * D_MODEL];
__device__ float g_K[(size_t)M_TOT * D_MODEL];
__device__ float g_V[(size_t)M_TOT * D_MODEL];

// ---------------- packed f32x2 helpers (attention kernel) ----------------
__device__ __forceinline__ u64 pk2(float lo, float hi) {
    u64 r; asm("mov.b64 %0,{%1,%2};" : "=l"(r) : "f"(lo), "f"(hi)); return r;
}
__device__ __forceinline__ u64 fma2(u64 a, u64 b, u64 c) {
    u64 d; asm("fma.rn.f32x2 %0,%1,%2,%3;" : "=l"(d) : "l"(a), "l"(b), "l"(c)); return d;
}
__device__ __forceinline__ u64 mul2(u64 a, u64 b) {
    u64 d; asm("mul.rn.f32x2 %0,%1,%2;" : "=l"(d) : "l"(a), "l"(b)); return d;
}
__device__ __forceinline__ void unpk(u64 a, float& x, float& y) {
    asm("mov.b64 {%0,%1},%2;" : "=f"(x), "=f"(y) : "l"(a));
}

// ---------------- baseline (sm_80+) primitives ----------------
__device__ __forceinline__ u32 smem_u32(const void* p) {
    u32 a; asm("{ .reg .u64 t; cvta.to.shared.u64 t, %1; cvt.u32.u64 %0, t; }"
               : "=r"(a) : "l"(p));
    return a;
}
__device__ __forceinline__ u32 rna_tf32(float x) {
    u32 r; asm("cvt.rna.tf32.f32 %0, %1;" : "=r"(r) : "f"(x)); return r;
}
__device__ __forceinline__ void cp16(u32 dst, const void* src) {
    asm volatile("cp.async.cg.shared.global [%0], [%1], 16;" :: "r"(dst), "l"(src));
}
__device__ __forceinline__ void cp_commit() {
    asm volatile("cp.async.commit_group;" ::: "memory");
}
template <int N> __device__ __forceinline__ void cp_wait() {
    asm volatile("cp.async.wait_group %0;" :: "n"(N) : "memory");
}
// D = A(16x8,row) * B(8x8,col) + D, tf32 inputs, fp32 accum.
__device__ __forceinline__ void mma_tf32(float* c, const u32* a, const u32* b) {
    asm volatile(
        "mma.sync.aligned.m16n8k8.row.col.f32.tf32.tf32.f32 "
        "{%0,%1,%2,%3},{%4,%5,%6,%7},{%8,%9},{%0,%1,%2,%3};"
        : "+f"(c[0]), "+f"(c[1]), "+f"(c[2]), "+f"(c[3])
        : "r"(a[0]), "r"(a[1]), "r"(a[2]), "r"(a[3]), "r"(b[0]), "r"(b[1]));
}

// =========================================================================
// Pre-convert: build rna-tf32 A = [Xs|Xt] and W_z = [W_zs|W_zt].
// =========================================================================
__global__ __launch_bounds__(256) void conv_A_kernel(
    const float* __restrict__ Xs, const float* __restrict__ Xt)
{
    int idx = blockIdx.x * 256 + threadIdx.x;          // over 8192*512 float4
    if (idx >= M_TOT * (K_TOT / 4)) return;
    int row = idx >> 9, c4 = idx & 511;
    const float* src = (c4 < 256) ? &Xs[(size_t)row * 1024 + c4 * 4]
                                  : &Xt[(size_t)row * 1024 + (c4 - 256) * 4];
    float4 v = *(const float4*)src;
    uint4 o = make_uint4(rna_tf32(v.x), rna_tf32(v.y), rna_tf32(v.z), rna_tf32(v.w));
    *(uint4*)&g_A[(size_t)row * K_TOT + c4 * 4] = o;
}

__global__ __launch_bounds__(256) void conv_W_kernel(
    const float* __restrict__ Wqs, const float* __restrict__ Wqt,
    const float* __restrict__ Wks, const float* __restrict__ Wkt,
    const float* __restrict__ Wvs, const float* __restrict__ Wvt)
{
    int z = blockIdx.z;
    const float *Wa, *Wb;
    if (z == 0)      { Wa = Wqs; Wb = Wqt; }
    else if (z == 1) { Wa = Wks; Wb = Wkt; }
    else             { Wa = Wvs; Wb = Wvt; }
    int idx = blockIdx.x * 256 + threadIdx.x;          // over 1024*512 float4
    if (idx >= D_MODEL * (K_TOT / 4)) return;
    int row = idx >> 9, c4 = idx & 511;
    const float* src = (c4 < 256) ? &Wa[(size_t)row * 1024 + c4 * 4]
                                  : &Wb[(size_t)row * 1024 + (c4 - 256) * 4];
    float4 v = *(const float4*)src;
    uint4 o = make_uint4(rna_tf32(v.x), rna_tf32(v.y), rna_tf32(v.z), rna_tf32(v.w));
    *(uint4*)&g_W[z][(size_t)row * K_TOT + c4 * 4] = o;
}

// =========================================================================
// Projection GEMM via legacy tensor path (mma.sync tf32).
//   out_z[m,n] = sum_k A[m,k] * W_z[n,k] + bias_z[n]
// CTA tile 128(M) x 256(N), 256 threads = 8 warps (2m x 4n), warp 64x64.
// K-chunk 32, 2-stage cp.async double buffer.
// grid = (64, 4, 3).
// =========================================================================
#define PJ_KC     32
#define PJ_NK     (K_TOT / PJ_KC)     /* 64 */
#define ROW_F     36                  /* smem row stride in floats (pad 4) */
#define STG_A     (128 * ROW_F * 4)   /* 18432 B */
#define STG_B     (256 * ROW_F * 4)   /* 36864 B */
#define STG_SZ    (STG_A + STG_B)     /* 55296 B */
#define SM_BIAS   (2 * STG_SZ)        /* 110592 */
#define SM_TOTAL  (SM_BIAS + 1024 + 64)

__global__ void __launch_bounds__(256, 1) proj_mma_kernel(
    const float* __restrict__ bqs, const float* __restrict__ bqt,
    const float* __restrict__ bks, const float* __restrict__ bkt,
    const float* __restrict__ bvs, const float* __restrict__ bvt,
    float* __restrict__ oQ, float* __restrict__ oK, float* __restrict__ oV)
{
    extern __shared__ char sm[];
    const u32 smb = smem_u32(sm);
    const int t    = threadIdx.x;
    const int wid  = t >> 5;
    const int lane = t & 31;
    const int g    = lane >> 2;        // group id (0..7)
    const int c    = lane & 3;         // thread-in-group (0..3)
    const int wm   = (wid >> 2) * 64;  // warp m offset (0 or 64)
    const int wn   = (wid & 3) * 64;   // warp n offset (0..192)
    const int m0   = blockIdx.x * 128;
    const int n0   = blockIdx.y * 256;
    const int z    = blockIdx.z;

    const float* bA; const float* bB; float* outp;
    if (z == 0)      { bA = bqs; bB = bqt; outp = oQ; }
    else if (z == 1) { bA = bks; bB = bkt; outp = oK; }
    else             { bA = bvs; bB = bvt; outp = oV; }

    const float* gAp = g_A;
    const float* gWp = g_W[z];

    // bias into smem
    if (t < 64) {
        float4 a = *(const float4*)&bA[n0 + t * 4];
        float4 b = *(const float4*)&bB[n0 + t * 4];
        *(float4*)(sm + SM_BIAS + t * 16) =
            make_float4(a.x + b.x, a.y + b.y, a.z + b.z, a.w + b.w);
    }

    float acc[4][8][4];
    #pragma unroll
    for (int mt = 0; mt < 4; ++mt)
        #pragma unroll
        for (int nt = 0; nt < 8; ++nt)
            #pragma unroll
            for (int j = 0; j < 4; ++j) acc[mt][nt][j] = 0.f;

    // ---- cp.async issue helper (chunk i -> stage i&1) ----
    auto issue = [&](int i) {
        const int s = i & 1;
        const int kc = i * PJ_KC;
        const u32 abase = smb + s * STG_SZ;
        const u32 bbase = abase + STG_A;
        #pragma unroll
        for (int j = 0; j < 4; ++j) {               // A: 1024 x 16B
            int sid = t + j * 256;
            int row = sid >> 3, sc = sid & 7;
            cp16(abase + row * (ROW_F * 4) + sc * 16,
                 &gAp[(size_t)(m0 + row) * K_TOT + kc + sc * 4]);
        }
        #pragma unroll
        for (int j = 0; j < 8; ++j) {               // B: 2048 x 16B
            int sid = t + j * 256;
            int row = sid >> 3, sc = sid & 7;
            cp16(bbase + row * (ROW_F * 4) + sc * 16,
                 &gWp[(size_t)(n0 + row) * K_TOT + kc + sc * 4]);
        }
        cp_commit();
    };

    issue(0);

    #pragma unroll 1
    for (int i = 0; i < PJ_NK; ++i) {
        if (i + 1 < PJ_NK) { issue(i + 1); cp_wait<1>(); }
        else               { cp_wait<0>(); }
        __syncthreads();

        const int s = i & 1;
        const u32* As = (const u32*)(sm + s * STG_SZ);
        const u32* Bs = (const u32*)(sm + s * STG_SZ + STG_A);

        #pragma unroll
        for (int ks = 0; ks < 4; ++ks) {
            u32 a[4][4], b[8][2];
            #pragma unroll
            for (int mt = 0; mt < 4; ++mt) {
                const u32* ap = As + (wm + mt * 16 + g) * ROW_F + ks * 8 + c;
                a[mt][0] = ap[0];
                a[mt][1] = ap[8 * ROW_F];
                a[mt][2] = ap[4];
                a[mt][3] = ap[8 * ROW_F + 4];
            }
            #pragma unroll
            for (int nt = 0; nt < 8; ++nt) {
                const u32* bp = Bs + (wn + nt * 8 + g) * ROW_F + ks * 8 + c;
                b[nt][0] = bp[0];
                b[nt][1] = bp[4];
            }
            #pragma unroll
            for (int mt = 0; mt < 4; ++mt)
                #pragma unroll
                for (int nt = 0; nt < 8; ++nt)
                    mma_tf32(acc[mt][nt], a[mt], b[nt]);
        }
        __syncthreads();   // stage s about to be overwritten by issue(i+2)
    }

    // ---- epilogue: C + bias -> out ----
    const float* bias = (const float*)(sm + SM_BIAS);
    #pragma unroll
    for (int mt = 0; mt < 4; ++mt) {
        #pragma unroll
        for (int nt = 0; nt < 8; ++nt) {
            int cc = wn + nt * 8 + 2 * c;
            int r0 = m0 + wm + mt * 16 + g;
            float b0 = bias[cc], b1 = bias[cc + 1];
            float2 v0 = make_float2(acc[mt][nt][0] + b0, acc[mt][nt][1] + b1);
            float2 v1 = make_float2(acc[mt][nt][2] + b0, acc[mt][nt][3] + b1);
            *(float2*)&outp[(size_t)r0 * D_MODEL + n0 + cc] = v0;
            *(float2*)&outp[(size_t)(r0 + 8) * D_MODEL + n0 + cc] = v1;
        }
    }
}

// =========================================================================
// Flash attention, fp32, f32x2 inner products (unchanged — passing R1).
// =========================================================================
#define AT_PAD 68
#define ATTN_SMEM (4 * 64 * AT_PAD * 4)   /* 69632 B */

__global__ __launch_bounds__(256) void attn_kernel(
    const float* __restrict__ Q, const float* __restrict__ K,
    const float* __restrict__ V, float* __restrict__ out,
    const float* __restrict__ biasp)
{
    extern __shared__ float smf[];
    float (*Qs)[AT_PAD] = (float(*)[AT_PAD])(smf);
    float (*Ks)[AT_PAD] = (float(*)[AT_PAD])(smf + 64 * AT_PAD);
    float (*Ps)[AT_PAD] = (float(*)[AT_PAD])(smf + 2 * 64 * AT_PAD);
    float (*Vs)[AT_PAD] = (float(*)[AT_PAD])(smf + 3 * 64 * AT_PAD);

    const int t  = threadIdx.x;
    const int tx = t & 15, ty = t >> 4;
    const int q0 = blockIdx.x * 64;
    const int bh = blockIdx.y;
    const int b  = bh >> 4, h = bh & 15;
    const size_t base = (size_t)b * S_LEN * D_MODEL + (size_t)h * DKH;
    const float bias  = biasp[0];
    const float NEGINF = __int_as_float(0xff800000);

    #pragma unroll
    for (int l = 0; l < 4; ++l) {
        int f = t + l * 256;
        int r = f >> 4, seg = f & 15;
        float4 v = *(const float4*)&Q[base + (size_t)(q0 + r) * D_MODEL + seg * 4];
        Qs[seg*4+0][r] = v.x; Qs[seg*4+1][r] = v.y;
        Qs[seg*4+2][r] = v.z; Qs[seg*4+3][r] = v.w;
    }

    float mrow[4], lrow[4];
    u64 oacc[4][2];
    #pragma unroll
    for (int r = 0; r < 4; ++r) {
        mrow[r] = NEGINF; lrow[r] = 0.f;
        oacc[r][0] = 0ull; oacc[r][1] = 0ull;
    }

    #pragma unroll 1
    for (int kb = 0; kb < S_LEN / 64; ++kb) {
        const int c0 = kb * 64;
        __syncthreads();
        #pragma unroll
        for (int l = 0; l < 4; ++l) {
            int f = t + l * 256;
            int r = f >> 4, seg = f & 15;
            float4 kv = *(const float4*)&K[base + (size_t)(c0 + r) * D_MODEL + seg * 4];
            Ks[seg*4+0][r] = kv.x; Ks[seg*4+1][r] = kv.y;
            Ks[seg*4+2][r] = kv.z; Ks[seg*4+3][r] = kv.w;
            float4 vv = *(const float4*)&V[base + (size_t)(c0 + r) * D_MODEL + seg * 4];
            *(float4*)&Vs[r][seg * 4] = vv;
        }
        __syncthreads();

        u64 sacc[4][2];
        #pragma unroll
        for (int r = 0; r < 4; ++r) { sacc[r][0] = 0ull; sacc[r][1] = 0ull; }
        #pragma unroll 8
        for (int d = 0; d < 64; ++d) {
            float4 q = *(const float4*)&Qs[d][ty * 4];
            u64 k0 = *(const u64*)&Ks[d][tx * 4];
            u64 k1 = *(const u64*)&Ks[d][tx * 4 + 2];
            float qa[4] = {q.x, q.y, q.z, q.w};
            #pragma unroll
            for (int r = 0; r < 4; ++r) {
                u64 qd = pk2(qa[r], qa[r]);
                sacc[r][0] = fma2(qd, k0, sacc[r][0]);
                sacc[r][1] = fma2(qd, k1, sacc[r][1]);
            }
        }

        #pragma unroll
        for (int r = 0; r < 4; ++r) {
            float s0, s1, s2, s3;
            unpk(sacc[r][0], s0, s1);
            unpk(sacc[r][1], s2, s3);
            s0 = s0 * 0.125f + bias; s1 = s1 * 0.125f + bias;
            s2 = s2 * 0.125f + bias; s3 = s3 * 0.125f + bias;
            float mx = fmaxf(fmaxf(s0, s1), fmaxf(s2, s3));
            #pragma unroll
            for (int o = 1; o < 16; o <<= 1)
                mx = fmaxf(mx, __shfl_xor_sync(0xffffffffu, mx, o));
            float mnew = fmaxf(mrow[r], mx);
            float p0 = __expf(s0 - mnew), p1 = __expf(s1 - mnew);
            float p2 = __expf(s2 - mnew), p3 = __expf(s3 - mnew);
            float ls = (p0 + p1) + (p2 + p3);
            #pragma unroll
            for (int o = 1; o < 16; o <<= 1)
                ls += __shfl_xor_sync(0xffffffffu, ls, o);
            float fac = __expf(mrow[r] - mnew);
            lrow[r] = lrow[r] * fac + ls;
            mrow[r] = mnew;
            u64 fd = pk2(fac, fac);
            oacc[r][0] = mul2(oacc[r][0], fd);
            oacc[r][1] = mul2(oacc[r][1], fd);
            Ps[tx*4+0][ty*4+r] = p0;
            Ps[tx*4+1][ty*4+r] = p1;
            Ps[tx*4+2][ty*4+r] = p2;
            Ps[tx*4+3][ty*4+r] = p3;
        }
        __syncthreads();

        #pragma unroll 8
        for (int cI = 0; cI < 64; ++cI) {
            float4 p = *(const float4*)&Ps[cI][ty * 4];
            u64 v0 = *(const u64*)&Vs[cI][tx * 4];
            u64 v1 = *(const u64*)&Vs[cI][tx * 4 + 2];
            float pa[4] = {p.x, p.y, p.z, p.w};
            #pragma unroll
            for (int r = 0; r < 4; ++r) {
                u64 pd = pk2(pa[r], pa[r]);
                oacc[r][0] = fma2(pd, v0, oacc[r][0]);
                oacc[r][1] = fma2(pd, v1, oacc[r][1]);
            }
        }
    }

    #pragma unroll
    for (int r = 0; r < 4; ++r) {
        float inv = 1.0f / lrow[r];
        float o0, o1, o2, o3;
        unpk(oacc[r][0], o0, o1);
        unpk(oacc[r][1], o2, o3);
        float4 st = {o0 * inv, o1 * inv, o2 * inv, o3 * inv};
        *(float4*)&out[base + (size_t)(q0 + ty * 4 + r) * D_MODEL + tx * 4] = st;
    }
}

// =========================================================================
extern "C" void kernel_launch(void* const* d_in, const int* in_sizes, int n_in,
                              void* d_out, int out_size)
{
    (void)in_sizes; (void)n_in; (void)out_size;
    const float* Xs   = (const float*)d_in[0];
    const float* Xt   = (const float*)d_in[1];
    const float* W_qs = (const float*)d_in[2];
    const float* b_qs = (const float*)d_in[3];
    const float* W_qt = (const float*)d_in[4];
    const float* b_qt = (const float*)d_in[5];
    const float* W_ks = (const float*)d_in[6];
    const float* b_ks = (const float*)d_in[7];
    const float* W_kt = (const float*)d_in[8];
    const float* b_kt = (const float*)d_in[9];
    const float* W_vs = (const float*)d_in[10];
    const float* b_vs = (const float*)d_in[11];
    const float* W_vt = (const float*)d_in[12];
    const float* b_vt = (const float*)d_in[13];
    const float* abias = (const float*)d_in[14];
    float* out = (float*)d_out;

    float *Qp, *Kp, *Vp;
    cudaGetSymbolAddress((void**)&Qp, g_Q);
    cudaGetSymbolAddress((void**)&Kp, g_K);
    cudaGetSymbolAddress((void**)&Vp, g_V);

    // 1) rna-tf32 pre-convert of A and W (one-time, ~50-70us)
    conv_A_kernel<<<(M_TOT * (K_TOT / 4) + 255) / 256, 256>>>(Xs, Xt);
    conv_W_kernel<<<dim3((D_MODEL * (K_TOT / 4) + 255) / 256, 1, 3), 256>>>(
        W_qs, W_qt, W_ks, W_kt, W_vs, W_vt);

    // 2) tensor-core projections (legacy mma.sync tf32)
    cudaFuncSetAttribute(proj_mma_kernel,
                         cudaFuncAttributeMaxDynamicSharedMemorySize, SM_TOTAL);
    proj_mma_kernel<<<dim3(M_TOT / 128, D_MODEL / 256, 3), 256, SM_TOTAL>>>(
        b_qs, b_qt, b_ks, b_kt, b_vs, b_vt, Qp, Kp, Vp);

    // 3) attention (SIMT f32x2, unchanged)
    cudaFuncSetAttribute(attn_kernel,
                         cudaFuncAttributeMaxDynamicSharedMemorySize, ATTN_SMEM);
    attn_kernel<<<dim3(S_LEN / 64, NBATCH * NH), 256, ATTN_SMEM>>>(
        Qp, Kp, Vp, out, abias);
}

// round 9
// speedup vs baseline: 2.8190x; 1.8380x over previous
#include <cuda_runtime.h>
#include <cstdint>

typedef unsigned long long u64;
typedef unsigned int u32;
typedef unsigned short u16;

#define D_MODEL 1024
#define S_LEN   2048
#define NBATCH  4
#define NH      16
#define DKH     64
#define M_TOT   (NBATCH * S_LEN)   /* 8192 */
#define K_TOT   2048               /* concat of Xs|Xt feature dims */

// Scratch (no allocs): tf32-rounded operands + projected Q/K/V.
__device__ float g_A[(size_t)M_TOT * K_TOT];            // [Xs|Xt], rna-tf32
__device__ float g_W[3][(size_t)D_MODEL * K_TOT];       // [W_zs|W_zt], rna-tf32
__device__ float g_Q[(size_t)M_TOT * D_MODEL];
__device__ float g_K[(size_t)M_TOT * D_MODEL];
__device__ float g_V[(size_t)M_TOT * D_MODEL];

// ---------------- baseline (sm_80+) primitives ----------------
__device__ __forceinline__ u32 smem_u32(const void* p) {
    u32 a; asm("{ .reg .u64 t; cvta.to.shared.u64 t, %1; cvt.u32.u64 %0, t; }"
               : "=r"(a) : "l"(p));
    return a;
}
__device__ __forceinline__ u32 rna_tf32(float x) {
    u32 r; asm("cvt.rna.tf32.f32 %0, %1;" : "=r"(r) : "f"(x)); return r;
}
__device__ __forceinline__ void cp16(u32 dst, const void* src) {
    asm volatile("cp.async.cg.shared.global [%0], [%1], 16;" :: "r"(dst), "l"(src));
}
__device__ __forceinline__ void cp_commit() {
    asm volatile("cp.async.commit_group;" ::: "memory");
}
template <int N> __device__ __forceinline__ void cp_wait() {
    asm volatile("cp.async.wait_group %0;" :: "n"(N) : "memory");
}
// tf32: D = A(16x8,row) * B(8x8,col) + D
__device__ __forceinline__ void mma_tf32(float* c, const u32* a, const u32* b) {
    asm volatile(
        "mma.sync.aligned.m16n8k8.row.col.f32.tf32.tf32.f32 "
        "{%0,%1,%2,%3},{%4,%5,%6,%7},{%8,%9},{%0,%1,%2,%3};"
        : "+f"(c[0]), "+f"(c[1]), "+f"(c[2]), "+f"(c[3])
        : "r"(a[0]), "r"(a[1]), "r"(a[2]), "r"(a[3]), "r"(b[0]), "r"(b[1]));
}
// bf16: D = A(16x16,row) * B(16x8,col) + D
__device__ __forceinline__ void mma_bf16(float* c, const u32* a, u32 b0, u32 b1) {
    asm volatile(
        "mma.sync.aligned.m16n8k16.row.col.f32.bf16.bf16.f32 "
        "{%0,%1,%2,%3},{%4,%5,%6,%7},{%8,%9},{%0,%1,%2,%3};"
        : "+f"(c[0]), "+f"(c[1]), "+f"(c[2]), "+f"(c[3])
        : "r"(a[0]), "r"(a[1]), "r"(a[2]), "r"(a[3]), "r"(b0), "r"(b1));
}
#define LDSM4(r0, r1, r2, r3, a)                                             \
    asm volatile("ldmatrix.sync.aligned.m8n8.x4.shared.b16 {%0,%1,%2,%3},[%4];" \
        : "=r"(r0), "=r"(r1), "=r"(r2), "=r"(r3) : "r"(a))
#define LDSM4T(r0, r1, r2, r3, a)                                            \
    asm volatile("ldmatrix.sync.aligned.m8n8.x4.trans.shared.b16 {%0,%1,%2,%3},[%4];" \
        : "=r"(r0), "=r"(r1), "=r"(r2), "=r"(r3) : "r"(a))

// bf16 pack/unpack (hi goes to upper 16 bits)
__device__ __forceinline__ u32 bf16x2(float hi, float lo) {
    u32 d; asm("cvt.rn.bf16x2.f32 %0,%1,%2;" : "=r"(d) : "f"(hi), "f"(lo)); return d;
}
__device__ __forceinline__ float bflo(u32 x) { return __uint_as_float(x << 16); }
__device__ __forceinline__ float bfhi(u32 x) { return __uint_as_float(x & 0xffff0000u); }

// =========================================================================
// Pre-convert: build rna-tf32 A = [Xs|Xt] and W_z = [W_zs|W_zt].
// =========================================================================
__global__ __launch_bounds__(256) void conv_A_kernel(
    const float* __restrict__ Xs, const float* __restrict__ Xt)
{
    int idx = blockIdx.x * 256 + threadIdx.x;          // over 8192*512 float4
    if (idx >= M_TOT * (K_TOT / 4)) return;
    int row = idx >> 9, c4 = idx & 511;
    const float* src = (c4 < 256) ? &Xs[(size_t)row * 1024 + c4 * 4]
                                  : &Xt[(size_t)row * 1024 + (c4 - 256) * 4];
    float4 v = *(const float4*)src;
    uint4 o = make_uint4(rna_tf32(v.x), rna_tf32(v.y), rna_tf32(v.z), rna_tf32(v.w));
    *(uint4*)&g_A[(size_t)row * K_TOT + c4 * 4] = o;
}

__global__ __launch_bounds__(256) void conv_W_kernel(
    const float* __restrict__ Wqs, const float* __restrict__ Wqt,
    const float* __restrict__ Wks, const float* __restrict__ Wkt,
    const float* __restrict__ Wvs, const float* __restrict__ Wvt)
{
    int z = blockIdx.z;
    const float *Wa, *Wb;
    if (z == 0)      { Wa = Wqs; Wb = Wqt; }
    else if (z == 1) { Wa = Wks; Wb = Wkt; }
    else             { Wa = Wvs; Wb = Wvt; }
    int idx = blockIdx.x * 256 + threadIdx.x;          // over 1024*512 float4
    if (idx >= D_MODEL * (K_TOT / 4)) return;
    int row = idx >> 9, c4 = idx & 511;
    const float* src = (c4 < 256) ? &Wa[(size_t)row * 1024 + c4 * 4]
                                  : &Wb[(size_t)row * 1024 + (c4 - 256) * 4];
    float4 v = *(const float4*)src;
    uint4 o = make_uint4(rna_tf32(v.x), rna_tf32(v.y), rna_tf32(v.z), rna_tf32(v.w));
    *(uint4*)&g_W[z][(size_t)row * K_TOT + c4 * 4] = o;
}

// =========================================================================
// Projection GEMM via legacy tensor path (mma.sync tf32).  (unchanged R8)
// =========================================================================
#define PJ_KC     32
#define PJ_NK     (K_TOT / PJ_KC)     /* 64 */
#define ROW_F     36
#define STG_A     (128 * ROW_F * 4)
#define STG_B     (256 * ROW_F * 4)
#define STG_SZ    (STG_A + STG_B)
#define SM_BIAS   (2 * STG_SZ)
#define SM_TOTAL  (SM_BIAS + 1024 + 64)

__global__ void __launch_bounds__(256, 1) proj_mma_kernel(
    const float* __restrict__ bqs, const float* __restrict__ bqt,
    const float* __restrict__ bks, const float* __restrict__ bkt,
    const float* __restrict__ bvs, const float* __restrict__ bvt,
    float* __restrict__ oQ, float* __restrict__ oK, float* __restrict__ oV)
{
    extern __shared__ char sm[];
    const u32 smb = smem_u32(sm);
    const int t    = threadIdx.x;
    const int wid  = t >> 5;
    const int lane = t & 31;
    const int g    = lane >> 2;
    const int c    = lane & 3;
    const int wm   = (wid >> 2) * 64;
    const int wn   = (wid & 3) * 64;
    const int m0   = blockIdx.x * 128;
    const int n0   = blockIdx.y * 256;
    const int z    = blockIdx.z;

    const float* bA; const float* bB; float* outp;
    if (z == 0)      { bA = bqs; bB = bqt; outp = oQ; }
    else if (z == 1) { bA = bks; bB = bkt; outp = oK; }
    else             { bA = bvs; bB = bvt; outp = oV; }

    const float* gAp = g_A;
    const float* gWp = g_W[z];

    if (t < 64) {
        float4 a = *(const float4*)&bA[n0 + t * 4];
        float4 b = *(const float4*)&bB[n0 + t * 4];
        *(float4*)(sm + SM_BIAS + t * 16) =
            make_float4(a.x + b.x, a.y + b.y, a.z + b.z, a.w + b.w);
    }

    float acc[4][8][4];
    #pragma unroll
    for (int mt = 0; mt < 4; ++mt)
        #pragma unroll
        for (int nt = 0; nt < 8; ++nt)
            #pragma unroll
            for (int j = 0; j < 4; ++j) acc[mt][nt][j] = 0.f;

    auto issue = [&](int i) {
        const int s = i & 1;
        const int kc = i * PJ_KC;
        const u32 abase = smb + s * STG_SZ;
        const u32 bbase = abase + STG_A;
        #pragma unroll
        for (int j = 0; j < 4; ++j) {
            int sid = t + j * 256;
            int row = sid >> 3, sc = sid & 7;
            cp16(abase + row * (ROW_F * 4) + sc * 16,
                 &gAp[(size_t)(m0 + row) * K_TOT + kc + sc * 4]);
        }
        #pragma unroll
        for (int j = 0; j < 8; ++j) {
            int sid = t + j * 256;
            int row = sid >> 3, sc = sid & 7;
            cp16(bbase + row * (ROW_F * 4) + sc * 16,
                 &gWp[(size_t)(n0 + row) * K_TOT + kc + sc * 4]);
        }
        cp_commit();
    };

    issue(0);

    #pragma unroll 1
    for (int i = 0; i < PJ_NK; ++i) {
        if (i + 1 < PJ_NK) { issue(i + 1); cp_wait<1>(); }
        else               { cp_wait<0>(); }
        __syncthreads();

        const int s = i & 1;
        const u32* As = (const u32*)(sm + s * STG_SZ);
        const u32* Bs = (const u32*)(sm + s * STG_SZ + STG_A);

        #pragma unroll
        for (int ks = 0; ks < 4; ++ks) {
            u32 a[4][4], b[8][2];
            #pragma unroll
            for (int mt = 0; mt < 4; ++mt) {
                const u32* ap = As + (wm + mt * 16 + g) * ROW_F + ks * 8 + c;
                a[mt][0] = ap[0];
                a[mt][1] = ap[8 * ROW_F];
                a[mt][2] = ap[4];
                a[mt][3] = ap[8 * ROW_F + 4];
            }
            #pragma unroll
            for (int nt = 0; nt < 8; ++nt) {
                const u32* bp = Bs + (wn + nt * 8 + g) * ROW_F + ks * 8 + c;
                b[nt][0] = bp[0];
                b[nt][1] = bp[4];
            }
            #pragma unroll
            for (int mt = 0; mt < 4; ++mt)
                #pragma unroll
                for (int nt = 0; nt < 8; ++nt)
                    mma_tf32(acc[mt][nt], a[mt], b[nt]);
        }
        __syncthreads();
    }

    const float* bias = (const float*)(sm + SM_BIAS);
    #pragma unroll
    for (int mt = 0; mt < 4; ++mt) {
        #pragma unroll
        for (int nt = 0; nt < 8; ++nt) {
            int cc = wn + nt * 8 + 2 * c;
            int r0 = m0 + wm + mt * 16 + g;
            float b0 = bias[cc], b1 = bias[cc + 1];
            float2 v0 = make_float2(acc[mt][nt][0] + b0, acc[mt][nt][1] + b1);
            float2 v1 = make_float2(acc[mt][nt][2] + b0, acc[mt][nt][3] + b1);
            *(float2*)&outp[(size_t)r0 * D_MODEL + n0 + cc] = v0;
            *(float2*)&outp[(size_t)(r0 + 8) * D_MODEL + n0 + cc] = v1;
        }
    }
}

// =========================================================================
// Flash attention on tensor cores, bf16x3 split (error ~2e-5, i.e. free).
// CTA: 128 q-rows x one (b,h); k-tiles of 128; 8 warps x 16 rows each.
// Q split-fragments in registers; P converts acc->A-frag in registers.
// =========================================================================
#define RS       72                    /* u16 row stride (144B, LDSM-safe) */
#define TILE_B   (128 * RS * 2)        /* 18432 B per bf16 tile */
#define ATT_SMEM (4 * TILE_B)          /* Kh,Kl,Vh,Vl = 73728 B */

__device__ __forceinline__ void load_cvt128(
    const float* __restrict__ src, u16* dh, u16* dl, int t)
{
    // 128 rows x 64 cols fp32 -> bf16 hi/lo splits
    int row = t >> 1;
    int c0  = (t & 1) * 32;
    const float* p = src + (size_t)row * D_MODEL + c0;
    u32* ph = (u32*)(dh + row * RS + c0);
    u32* pl = (u32*)(dl + row * RS + c0);
    #pragma unroll
    for (int i = 0; i < 8; ++i) {
        float4 v = *(const float4*)(p + i * 4);
        u32 h0 = bf16x2(v.y, v.x);
        u32 h1 = bf16x2(v.w, v.z);
        u32 l0 = bf16x2(v.y - bfhi(h0), v.x - bflo(h0));
        u32 l1 = bf16x2(v.w - bfhi(h1), v.z - bflo(h1));
        ph[i * 2] = h0; ph[i * 2 + 1] = h1;
        pl[i * 2] = l0; pl[i * 2 + 1] = l1;
    }
}

__global__ void __launch_bounds__(256, 1) attn_mma_kernel(
    const float* __restrict__ Q, const float* __restrict__ K,
    const float* __restrict__ V, float* __restrict__ out,
    const float* __restrict__ biasp)
{
    extern __shared__ char smc[];
    u16* Kh = (u16*)smc;
    u16* Kl = (u16*)(smc + TILE_B);
    u16* Vh = (u16*)(smc + 2 * TILE_B);
    u16* Vl = (u16*)(smc + 3 * TILE_B);
    const u32 khb = smem_u32(Kh), klb = smem_u32(Kl);
    const u32 vhb = smem_u32(Vh), vlb = smem_u32(Vl);

    const int t = threadIdx.x, w = t >> 5, lane = t & 31;
    const int g = lane >> 2, c2 = lane & 3;
    const int q0 = blockIdx.x * 128;
    const int bh = blockIdx.y, b = bh >> 4, h = bh & 15;
    const size_t base = (size_t)b * S_LEN * D_MODEL + (size_t)h * DKH;
    const float bias = biasp[0];
    const float NEGINF = __int_as_float(0xff800000);

    // ---- stage Q through Kh/Kl, pull split fragments into registers ----
    load_cvt128(Q + base + (size_t)q0 * D_MODEL, Kh, Kl, t);
    __syncthreads();
    u32 qh[4][4], ql[4][4];
    {
        int row = w * 16 + (lane & 15);
        int cb  = (lane >> 4) << 3;
        #pragma unroll
        for (int ks = 0; ks < 4; ++ks) {
            u32 ah = khb + (row * RS + ks * 16 + cb) * 2;
            u32 al = klb + (row * RS + ks * 16 + cb) * 2;
            LDSM4(qh[ks][0], qh[ks][1], qh[ks][2], qh[ks][3], ah);
            LDSM4(ql[ks][0], ql[ks][1], ql[ks][2], ql[ks][3], al);
        }
    }

    float m0r = NEGINF, m1r = NEGINF, l0r = 0.f, l1r = 0.f;
    float O[8][4];
    #pragma unroll
    for (int nt = 0; nt < 8; ++nt)
        #pragma unroll
        for (int j = 0; j < 4; ++j) O[nt][j] = 0.f;

    #pragma unroll 1
    for (int kb = 0; kb < S_LEN / 128; ++kb) {
        __syncthreads();   // prior tile's mma reads complete (and Q-frags on kb=0)
        load_cvt128(K + base + (size_t)(kb * 128) * D_MODEL, Kh, Kl, t);
        load_cvt128(V + base + (size_t)(kb * 128) * D_MODEL, Vh, Vl, t);
        __syncthreads();

        // ---- S = Q K^T : 16 n8-tiles per warp, bf16x3 ----
        float S[16][4];
        #pragma unroll
        for (int nt = 0; nt < 16; ++nt)
            #pragma unroll
            for (int j = 0; j < 4; ++j) S[nt][j] = 0.f;

        #pragma unroll
        for (int ks = 0; ks < 4; ++ks) {
            #pragma unroll
            for (int ntp = 0; ntp < 8; ++ntp) {
                int row = ntp * 16 + (lane & 7) + ((lane >> 4) << 3);
                int col = ks * 16 + (((lane >> 3) & 1) << 3);
                u32 bh4[4], bl4[4];
                LDSM4(bh4[0], bh4[1], bh4[2], bh4[3], khb + (row * RS + col) * 2);
                LDSM4(bl4[0], bl4[1], bl4[2], bl4[3], klb + (row * RS + col) * 2);
                mma_bf16(S[2*ntp],   qh[ks], bh4[0], bh4[1]);
                mma_bf16(S[2*ntp],   qh[ks], bl4[0], bl4[1]);
                mma_bf16(S[2*ntp],   ql[ks], bh4[0], bh4[1]);
                mma_bf16(S[2*ntp+1], qh[ks], bh4[2], bh4[3]);
                mma_bf16(S[2*ntp+1], qh[ks], bl4[2], bl4[3]);
                mma_bf16(S[2*ntp+1], ql[ks], bh4[2], bh4[3]);
            }
        }

        // ---- online softmax (rows r0=w*16+g, r1=r0+8; 4-lane row groups) ----
        float mx0 = NEGINF, mx1 = NEGINF;
        #pragma unroll
        for (int nt = 0; nt < 16; ++nt) {
            S[nt][0] = S[nt][0] * 0.125f + bias;
            S[nt][1] = S[nt][1] * 0.125f + bias;
            S[nt][2] = S[nt][2] * 0.125f + bias;
            S[nt][3] = S[nt][3] * 0.125f + bias;
            mx0 = fmaxf(mx0, fmaxf(S[nt][0], S[nt][1]));
            mx1 = fmaxf(mx1, fmaxf(S[nt][2], S[nt][3]));
        }
        mx0 = fmaxf(mx0, __shfl_xor_sync(0xffffffffu, mx0, 1));
        mx0 = fmaxf(mx0, __shfl_xor_sync(0xffffffffu, mx0, 2));
        mx1 = fmaxf(mx1, __shfl_xor_sync(0xffffffffu, mx1, 1));
        mx1 = fmaxf(mx1, __shfl_xor_sync(0xffffffffu, mx1, 2));
        float mn0 = fmaxf(m0r, mx0), mn1 = fmaxf(m1r, mx1);
        float f0 = __expf(m0r - mn0), f1 = __expf(m1r - mn1);
        m0r = mn0; m1r = mn1;
        #pragma unroll
        for (int nt = 0; nt < 8; ++nt) {
            O[nt][0] *= f0; O[nt][1] *= f0;
            O[nt][2] *= f1; O[nt][3] *= f1;
        }

        // ---- exp + pack + PV (P acc -> A-frags in registers) ----
        float s0 = 0.f, s1 = 0.f;
        #pragma unroll
        for (int j = 0; j < 8; ++j) {
            u32 aPh[4], aPl[4];
            #pragma unroll
            for (int q = 0; q < 2; ++q) {
                int nt = 2 * j + q;
                float p0 = __expf(S[nt][0] - mn0), p1 = __expf(S[nt][1] - mn0);
                float p2 = __expf(S[nt][2] - mn1), p3 = __expf(S[nt][3] - mn1);
                s0 += p0 + p1; s1 += p2 + p3;
                u32 H0 = bf16x2(p1, p0), H1 = bf16x2(p3, p2);
                u32 L0 = bf16x2(p1 - bfhi(H0), p0 - bflo(H0));
                u32 L1 = bf16x2(p3 - bfhi(H1), p2 - bflo(H1));
                aPh[2*q] = H0; aPh[2*q+1] = H1;
                aPl[2*q] = L0; aPl[2*q+1] = L1;
            }
            #pragma unroll
            for (int v = 0; v < 4; ++v) {
                int row = j * 16 + (lane & 7) + (((lane >> 3) & 1) << 3);
                int col = v * 16 + ((lane >> 4) << 3);
                u32 bvh[4], bvl[4];
                LDSM4T(bvh[0], bvh[1], bvh[2], bvh[3], vhb + (row * RS + col) * 2);
                LDSM4T(bvl[0], bvl[1], bvl[2], bvl[3], vlb + (row * RS + col) * 2);
                mma_bf16(O[2*v],   aPh, bvh[0], bvh[1]);
                mma_bf16(O[2*v],   aPh, bvl[0], bvl[1]);
                mma_bf16(O[2*v],   aPl, bvh[0], bvh[1]);
                mma_bf16(O[2*v+1], aPh, bvh[2], bvh[3]);
                mma_bf16(O[2*v+1], aPh, bvl[2], bvl[3]);
                mma_bf16(O[2*v+1], aPl, bvh[2], bvh[3]);
            }
        }
        s0 += __shfl_xor_sync(0xffffffffu, s0, 1);
        s0 += __shfl_xor_sync(0xffffffffu, s0, 2);
        s1 += __shfl_xor_sync(0xffffffffu, s1, 1);
        s1 += __shfl_xor_sync(0xffffffffu, s1, 2);
        l0r = l0r * f0 + s0;
        l1r = l1r * f1 + s1;
    }

    // ---- epilogue ----
    float i0 = 1.f / l0r, i1 = 1.f / l1r;
    int r0 = q0 + w * 16 + g;
    #pragma unroll
    for (int nt = 0; nt < 8; ++nt) {
        int cc = nt * 8 + c2 * 2;
        float2 v0 = make_float2(O[nt][0] * i0, O[nt][1] * i0);
        float2 v1 = make_float2(O[nt][2] * i1, O[nt][3] * i1);
        *(float2*)&out[base + (size_t)r0 * D_MODEL + cc] = v0;
        *(float2*)&out[base + (size_t)(r0 + 8) * D_MODEL + cc] = v1;
    }
}

// =========================================================================
extern "C" void kernel_launch(void* const* d_in, const int* in_sizes, int n_in,
                              void* d_out, int out_size)
{
    (void)in_sizes; (void)n_in; (void)out_size;
    const float* Xs   = (const float*)d_in[0];
    const float* Xt   = (const float*)d_in[1];
    const float* W_qs = (const float*)d_in[2];
    const float* b_qs = (const float*)d_in[3];
    const float* W_qt = (const float*)d_in[4];
    const float* b_qt = (const float*)d_in[5];
    const float* W_ks = (const float*)d_in[6];
    const float* b_ks = (const float*)d_in[7];
    const float* W_kt = (const float*)d_in[8];
    const float* b_kt = (const float*)d_in[9];
    const float* W_vs = (const float*)d_in[10];
    const float* b_vs = (const float*)d_in[11];
    const float* W_vt = (const float*)d_in[12];
    const float* b_vt = (const float*)d_in[13];
    const float* abias = (const float*)d_in[14];
    float* out = (float*)d_out;

    float *Qp, *Kp, *Vp;
    cudaGetSymbolAddress((void**)&Qp, g_Q);
    cudaGetSymbolAddress((void**)&Kp, g_K);
    cudaGetSymbolAddress((void**)&Vp, g_V);

    // 1) rna-tf32 pre-convert of A and W
    conv_A_kernel<<<(M_TOT * (K_TOT / 4) + 255) / 256, 256>>>(Xs, Xt);
    conv_W_kernel<<<dim3((D_MODEL * (K_TOT / 4) + 255) / 256, 1, 3), 256>>>(
        W_qs, W_qt, W_ks, W_kt, W_vs, W_vt);

    // 2) tensor-core projections (mma.sync tf32)
    cudaFuncSetAttribute(proj_mma_kernel,
                         cudaFuncAttributeMaxDynamicSharedMemorySize, SM_TOTAL);
    proj_mma_kernel<<<dim3(M_TOT / 128, D_MODEL / 256, 3), 256, SM_TOTAL>>>(
        b_qs, b_qt, b_ks, b_kt, b_vs, b_vt, Qp, Kp, Vp);

    // 3) tensor-core attention (bf16x3 split)
    cudaFuncSetAttribute(attn_mma_kernel,
                         cudaFuncAttributeMaxDynamicSharedMemorySize, ATT_SMEM);
    attn_mma_kernel<<<dim3(S_LEN / 128, NBATCH * NH), 256, ATT_SMEM>>>(
        Qp, Kp, Vp, out, abias);
}